// round 3
// baseline (speedup 1.0000x reference)
#include <cuda_runtime.h>
#include <math.h>

#define BATCH 128
#define HID   512
#define ATT   128
#define TT    256
#define CC    256
#define NEG_SLOPE 0.01f
#define NBLK  128
#define NTHR  256

// -------------------- device-global scratch (no allocs allowed) ----------------
__device__ float g_h1[BATCH * HID];
__device__ float g_c1[BATCH * HID];
__device__ float g_h2[BATCH * HID];
__device__ float g_c2[BATCH * HID];
__device__ float g_h3[BATCH * HID];
__device__ float g_c3[BATCH * HID];
__device__ float g_ctx[BATCH * ATT];
__device__ float g_part[8 * BATCH * 2048];    // split-K partials, gate GEMMs
__device__ float g_mpart[16 * BATCH * HID];   // split-K partials, mlp GEMM
__device__ unsigned g_flags[NBLK];            // grid barrier epochs (monotonic)

// -------------------- shared memory union --------------------------------------
struct GemmSmem { float As[32][132]; float Ws[32][132]; };
struct AttSmem  { float hs[HID]; float qs[ATT]; float at[TT]; float red[32]; };
struct ProjSmem { float ms[HID]; float red[32]; };
union SmemAll { GemmSmem g; AttSmem a; ProjSmem p; };

// -------------------- grid barrier ----------------------------------------------
__device__ __forceinline__ void st_rel(unsigned* p, unsigned v) {
    asm volatile("st.release.gpu.u32 [%0], %1;" :: "l"(p), "r"(v) : "memory");
}
__device__ __forceinline__ unsigned ld_acq(const unsigned* p) {
    unsigned v;
    asm volatile("ld.acquire.gpu.u32 %0, [%1];" : "=r"(v) : "l"(p) : "memory");
    return v;
}
__device__ __forceinline__ void gbar(unsigned target) {
    __syncthreads();
    if (threadIdx.x == 0) st_rel(&g_flags[blockIdx.x], target);
    if (threadIdx.x < NBLK) {
        while (ld_acq(&g_flags[threadIdx.x]) < target) __nanosleep(32);
    }
    __syncthreads();
}

// -------------------- reductions (256 threads) ----------------------------------
__device__ __forceinline__ float warpMax(float v) {
    #pragma unroll
    for (int o = 16; o; o >>= 1) v = fmaxf(v, __shfl_xor_sync(0xffffffffu, v, o));
    return v;
}
__device__ __forceinline__ float warpSum(float v) {
    #pragma unroll
    for (int o = 16; o; o >>= 1) v += __shfl_xor_sync(0xffffffffu, v, o);
    return v;
}
__device__ float blockMax(float v, float* red) {
    v = warpMax(v);
    if ((threadIdx.x & 31) == 0) red[threadIdx.x >> 5] = v;
    __syncthreads();
    if (threadIdx.x < 32) {
        float x = (threadIdx.x < 8) ? red[threadIdx.x] : -3.4e38f;
        x = warpMax(x);
        if (threadIdx.x == 0) red[0] = x;
    }
    __syncthreads();
    float r = red[0];
    __syncthreads();
    return r;
}
__device__ float blockSum(float v, float* red) {
    v = warpSum(v);
    if ((threadIdx.x & 31) == 0) red[threadIdx.x >> 5] = v;
    __syncthreads();
    if (threadIdx.x < 32) {
        float x = (threadIdx.x < 8) ? red[threadIdx.x] : 0.f;
        x = warpSum(x);
        if (threadIdx.x == 0) red[0] = x;
    }
    __syncthreads();
    float r = red[0];
    __syncthreads();
    return r;
}

// -------------------- GEMM phase -------------------------------------------------
// part[ks][BATCH][partN] = A_tile @ W_tile^T  (split-K, fixed combine order later)
// A virtual row m (all segment bounds multiples of 16):
//   k <  s0 : emb[Yin[m*ystride + t]][k]            (s0==0 disables)
//   k <  s1 : p1[m][k - s0]   (ld l1)
//   else    : p2[m][k - s1]   (ld l2)
// W virtual row n:  k < wk1 : W1[n][k] (ld wk1) ; else W2[n][k-wk1] (ld HID)
__device__ void gemm_phase(SmemAll& SS, int t,
    float* part, int partN, int ntN, int n32, int ksplit,
    const float* emb, const int* Yin, int ystride, int s0,
    const float* p1, int l1, int s1,
    const float* p2, int l2,
    const float* W1, int wk1, const float* W2)
{
    const int bid = blockIdx.x;
    if (bid >= ntN * ksplit) return;
    GemmSmem& S = SS.g;
    const int tid = threadIdx.x;
    const int nt = bid / ksplit;
    const int ks = bid % ksplit;
    const int N0 = nt * 128;
    const int q = n32 / ksplit, r = n32 % ksplit;
    const int cnt = q + (ks < r ? 1 : 0);
    const int t0 = ks * q + (ks < r ? ks : r);

    const int lm = tid & 127;           // load row (A: m, W: n-local)
    const int lk = (tid >> 7) << 4;     // load k offset (16 per thread)
    const int tx = tid & 15;
    const int ty = tid >> 4;

    float acc[2][4][2][4];              // [ri][i][ci][j]
    #pragma unroll
    for (int ri = 0; ri < 2; ri++)
        #pragma unroll
        for (int i = 0; i < 4; i++)
            #pragma unroll
            for (int ci = 0; ci < 2; ci++)
                #pragma unroll
                for (int j = 0; j < 4; j++) acc[ri][i][ci][j] = 0.f;

    for (int tt = 0; tt < cnt; tt++) {
        const int kb = (t0 + tt) * 32;
        __syncthreads();
        // A tile -> smem (transposed), conflict-free scalar stores
        #pragma unroll
        for (int i = 0; i < 4; i++) {
            const int gk = kb + lk + i * 4;
            const float* ap;
            if (gk < s0)      ap = emb + (size_t)Yin[lm * ystride + t] * HID + gk;
            else if (gk < s1) ap = p1 + (size_t)lm * l1 + (gk - s0);
            else              ap = p2 + (size_t)lm * l2 + (gk - s1);
            const float4 v = *reinterpret_cast<const float4*>(ap);
            S.As[lk + i * 4 + 0][lm] = v.x;
            S.As[lk + i * 4 + 1][lm] = v.y;
            S.As[lk + i * 4 + 2][lm] = v.z;
            S.As[lk + i * 4 + 3][lm] = v.w;
        }
        // W tile -> smem (transposed)
        #pragma unroll
        for (int i = 0; i < 4; i++) {
            const int gk = kb + lk + i * 4;
            const int n = N0 + lm;
            const float* wp = (gk < wk1)
                ? W1 + (size_t)n * wk1 + gk
                : W2 + (size_t)n * HID + (gk - wk1);
            const float4 v = *reinterpret_cast<const float4*>(wp);
            S.Ws[lk + i * 4 + 0][lm] = v.x;
            S.Ws[lk + i * 4 + 1][lm] = v.y;
            S.Ws[lk + i * 4 + 2][lm] = v.z;
            S.Ws[lk + i * 4 + 3][lm] = v.w;
        }
        __syncthreads();
        // 8x8 microtile FMA
        #pragma unroll 8
        for (int k = 0; k < 32; k++) {
            const float4 a0 = *reinterpret_cast<const float4*>(&S.As[k][ty * 4]);
            const float4 a1 = *reinterpret_cast<const float4*>(&S.As[k][ty * 4 + 64]);
            const float4 w0 = *reinterpret_cast<const float4*>(&S.Ws[k][tx * 4]);
            const float4 w1 = *reinterpret_cast<const float4*>(&S.Ws[k][tx * 4 + 64]);
            const float av[2][4] = {{a0.x, a0.y, a0.z, a0.w}, {a1.x, a1.y, a1.z, a1.w}};
            const float wv[2][4] = {{w0.x, w0.y, w0.z, w0.w}, {w1.x, w1.y, w1.z, w1.w}};
            #pragma unroll
            for (int ri = 0; ri < 2; ri++)
                #pragma unroll
                for (int i = 0; i < 4; i++)
                    #pragma unroll
                    for (int ci = 0; ci < 2; ci++)
                        #pragma unroll
                        for (int j = 0; j < 4; j++)
                            acc[ri][i][ci][j] += av[ri][i] * wv[ci][j];
        }
    }

    // epilogue: write split-K partials
    #pragma unroll
    for (int ri = 0; ri < 2; ri++)
        #pragma unroll
        for (int i = 0; i < 4; i++) {
            const int row = ri * 64 + ty * 4 + i;
            float* op = part + ((size_t)(ks * BATCH + row)) * partN + N0;
            #pragma unroll
            for (int ci = 0; ci < 2; ci++) {
                float4 v = make_float4(acc[ri][i][ci][0], acc[ri][i][ci][1],
                                       acc[ri][i][ci][2], acc[ri][i][ci][3]);
                *reinterpret_cast<float4*>(op + ci * 64 + tx * 4) = v;
            }
        }
}

// -------------------- LSTM pointwise update (block = batch row) -----------------
__device__ void update_phase(float* h, float* c, const float* bih, const float* bhh)
{
    const int b = blockIdx.x;
    const int tid = threadIdx.x;
    #pragma unroll
    for (int u = 0; u < 2; u++) {
        const int j = tid + u * 256;
        float gi = bih[j] + bhh[j];
        float gf = bih[j + 512] + bhh[j + 512];
        float gg = bih[j + 1024] + bhh[j + 1024];
        float go = bih[j + 1536] + bhh[j + 1536];
        #pragma unroll
        for (int ks = 0; ks < 8; ks++) {
            const float* pk = g_part + (size_t)(ks * BATCH + b) * 2048;
            gi += pk[j];
            gf += pk[j + 512];
            gg += pk[j + 1024];
            go += pk[j + 1536];
        }
        const float ig = 1.f / (1.f + expf(-gi));
        const float fg = 1.f / (1.f + expf(-gf));
        const float og = 1.f / (1.f + expf(-go));
        const float gv = tanhf(gg);
        const int idx = b * HID + j;
        const float cn = fg * c[idx] + ig * gv;
        c[idx] = cn;
        h[idx] = og * tanhf(cn);
    }
}

// -------------------- fused attention (block = batch row) -----------------------
__device__ void attend_phase(SmemAll& SS, const float* key, const float* value,
                             const int* flens, const float* Wq, const float* bq)
{
    AttSmem& A = SS.a;
    const int b = blockIdx.x;
    const int tid = threadIdx.x;

    A.hs[tid]       = g_h3[b * HID + tid];
    A.hs[tid + 256] = g_h3[b * HID + 256 + tid];
    __syncthreads();

    // q = h3 @ Wq^T + bq (2 threads per output a)
    {
        const int a = tid & 127;
        const int half = tid >> 7;
        const float* wr = Wq + (size_t)a * HID + half * 256;
        const float* hr = A.hs + half * 256;
        float s = 0.f;
        #pragma unroll 8
        for (int k = 0; k < 256; k += 4) {
            const float4 w = *reinterpret_cast<const float4*>(wr + k);
            s += w.x * hr[k] + w.y * hr[k + 1] + w.z * hr[k + 2] + w.w * hr[k + 3];
        }
        A.at[tid] = s;
    }
    __syncthreads();
    if (tid < ATT) A.qs[tid] = A.at[tid] + A.at[tid + 128] + bq[tid];
    __syncthreads();

    // energy at position t = tid
    float e = 0.f;
    {
        const float* kp = key + (size_t)b * ATT * TT + tid;
        #pragma unroll 8
        for (int a = 0; a < ATT; a++) e += A.qs[a] * kp[(size_t)a * TT];
    }
    const int flen = flens[b] >> 3;

    const float mx = blockMax(e, A.red);
    const float w = (tid < flen) ? expf(e - mx) : 0.f;
    const float sm = blockSum(w, A.red);
    A.at[tid] = w / sm;
    __syncthreads();

    // ctx = attn @ value (2 threads per output v)
    {
        const int v = tid & 127;
        const int half = tid >> 7;
        const float* vp = value + (size_t)b * TT * ATT + (size_t)(half * 128) * ATT + v;
        float cs = 0.f;
        #pragma unroll 8
        for (int t2 = 0; t2 < 128; t2++) cs += A.at[half * 128 + t2] * vp[(size_t)t2 * ATT];
        A.hs[tid] = cs;
    }
    __syncthreads();
    if (tid < ATT) g_ctx[b * ATT + tid] = A.hs[tid] + A.hs[tid + 128];
}

// -------------------- mlp-combine + projection + log-softmax --------------------
__device__ void proj_phase(SmemAll& SS, const float* emb, const float* bproj,
                           const float* bmlp, float* out, int t, int ml)
{
    ProjSmem& P = SS.p;
    const int b = blockIdx.x;
    const int tid = threadIdx.x;

    // combine mlp split-K partials + bias + LeakyReLU (fixed order => deterministic)
    #pragma unroll
    for (int u = 0; u < 2; u++) {
        const int j = tid + u * 256;
        float s = bmlp[j];
        #pragma unroll
        for (int ks = 0; ks < 16; ks++)
            s += g_mpart[((size_t)(ks * BATCH) + b) * HID + j];
        P.ms[j] = (s >= 0.f) ? s : NEG_SLOPE * s;
    }
    __syncthreads();

    // logits (class = tid) + log-softmax
    const float* er = emb + (size_t)tid * HID;
    float lg = bproj[tid];
    #pragma unroll 8
    for (int k = 0; k < HID; k += 4) {
        const float4 w = *reinterpret_cast<const float4*>(er + k);
        lg += w.x * P.ms[k] + w.y * P.ms[k + 1] + w.z * P.ms[k + 2] + w.w * P.ms[k + 3];
    }
    const float mx = blockMax(lg, P.red);
    const float ex = expf(lg - mx);
    const float sm = blockSum(ex, P.red);
    out[((size_t)b * ml + t) * CC + tid] = lg - mx - logf(sm);
    __syncthreads();   // protect smem before next phase reuses the union
}

// -------------------- persistent megakernel --------------------------------------
__global__ __launch_bounds__(NTHR, 1) void mega_kernel(
    const float* key, const float* value, const int* Yin, const int* flens,
    const float* emb, const float* Wq, const float* bq,
    const float* Wih1, const float* Whh1, const float* bih1, const float* bhh1,
    const float* Wih2, const float* Whh2, const float* bih2, const float* bhh2,
    const float* Wih3, const float* Whh3, const float* bih3, const float* bhh3,
    const float* Wmlp, const float* bmlp, const float* bproj,
    const float* h00, const float* h01, const float* h02,
    const float* c00, const float* c01, const float* c02,
    float* out, int ml, int ystride)
{
    __shared__ SmemAll S;
    const unsigned base = g_flags[blockIdx.x];   // monotonic epochs across replays
    unsigned bn = 0;

    // init state (broadcast initial h/c)
    {
        const int gidx = blockIdx.x * NTHR + threadIdx.x;   // 0..32767
        #pragma unroll
        for (int u = 0; u < 2; u++) {
            const int idx = gidx + u * 32768;
            const int j = idx & 511;
            g_h1[idx] = h00[j]; g_h2[idx] = h01[j]; g_h3[idx] = h02[j];
            g_c1[idx] = c00[j]; g_c2[idx] = c01[j]; g_c3[idx] = c02[j];
        }
    }
    gbar(base + ++bn);
    attend_phase(S, key, value, flens, Wq, bq);
    gbar(base + ++bn);

    for (int t = 0; t < ml; t++) {
        // LSTM1: A = [emb[y_t] | ctx | h1], W = [Wih1 | Whh1], K=1152
        gemm_phase(S, t, g_part, 2048, 16, 36, 8,
                   emb, Yin, ystride, 512,
                   g_ctx, ATT, 640, g_h1, HID,
                   Wih1, 640, Whh1);
        gbar(base + ++bn);
        update_phase(g_h1, g_c1, bih1, bhh1);
        gbar(base + ++bn);

        // LSTM2: A = [h1 | h2], K=1024
        gemm_phase(S, t, g_part, 2048, 16, 32, 8,
                   nullptr, nullptr, 0, 0,
                   g_h1, HID, 512, g_h2, HID,
                   Wih2, 512, Whh2);
        gbar(base + ++bn);
        update_phase(g_h2, g_c2, bih2, bhh2);
        gbar(base + ++bn);

        // LSTM3: A = [h2 | h3], K=1024
        gemm_phase(S, t, g_part, 2048, 16, 32, 8,
                   nullptr, nullptr, 0, 0,
                   g_h2, HID, 512, g_h3, HID,
                   Wih3, 512, Whh3);
        gbar(base + ++bn);
        update_phase(g_h3, g_c3, bih3, bhh3);
        gbar(base + ++bn);

        // attention from new h3
        attend_phase(S, key, value, flens, Wq, bq);
        gbar(base + ++bn);

        // mlp: A = [h3 | ctx], W = Wmlp, K=640, N=512, split-K 16
        gemm_phase(S, t, g_mpart, HID, 4, 20, 16,
                   nullptr, nullptr, 0, 0,
                   g_h3, HID, 512, g_ctx, ATT,
                   Wmlp, 640, nullptr);
        gbar(base + ++bn);

        // combine + LeakyReLU + tied projection + log-softmax
        proj_phase(S, emb, bproj, bmlp, out, t, ml);
        // no grid barrier needed: next gemm touches none of proj's data
    }
}

// -------------------- launch ------------------------------------------------------
extern "C" void kernel_launch(void* const* d_in, const int* in_sizes, int n_in,
                              void* d_out, int out_size)
{
    const float* key        = (const float*)d_in[0];
    const float* value      = (const float*)d_in[1];
    const int*   Yinput     = (const int*)d_in[2];
    const int*   frame_lens = (const int*)d_in[3];
    // d_in[4] = max_len scalar; derived from out_size instead
    const float* emb   = (const float*)d_in[5];
    const float* Wq    = (const float*)d_in[6];
    const float* bq    = (const float*)d_in[7];
    const float* Wih1  = (const float*)d_in[8];
    const float* Whh1  = (const float*)d_in[9];
    const float* bih1  = (const float*)d_in[10];
    const float* bhh1  = (const float*)d_in[11];
    const float* Wih2  = (const float*)d_in[12];
    const float* Whh2  = (const float*)d_in[13];
    const float* bih2  = (const float*)d_in[14];
    const float* bhh2  = (const float*)d_in[15];
    const float* Wih3  = (const float*)d_in[16];
    const float* Whh3  = (const float*)d_in[17];
    const float* bih3  = (const float*)d_in[18];
    const float* bhh3  = (const float*)d_in[19];
    const float* Wmlp  = (const float*)d_in[20];
    const float* bmlp  = (const float*)d_in[21];
    const float* bproj = (const float*)d_in[22];
    const float* h00 = (const float*)d_in[23];
    const float* h01 = (const float*)d_in[24];
    const float* h02 = (const float*)d_in[25];
    const float* c00 = (const float*)d_in[26];
    const float* c01 = (const float*)d_in[27];
    const float* c02 = (const float*)d_in[28];

    float* out = (float*)d_out;
    const int ml = out_size / (BATCH * CC);     // 300
    const int ystride = in_sizes[2] / BATCH;    // MAXLEN = 300

    mega_kernel<<<NBLK, NTHR>>>(
        key, value, Yinput, frame_lens,
        emb, Wq, bq,
        Wih1, Whh1, bih1, bhh1,
        Wih2, Whh2, bih2, bhh2,
        Wih3, Whh3, bih3, bhh3,
        Wmlp, bmlp, bproj,
        h00, h01, h02, c00, c01, c02,
        out, ml, ystride);
}